// round 1
// baseline (speedup 1.0000x reference)
#include <cuda_runtime.h>
#include <math.h>

// Problem constants
#define BATCH 64
#define C 128
#define HW 3136           // 56*56
#define NPART 4
#define KPART (HW / NPART)  // 784
#define NUM_ITER 5
#define TRIU 8256         // 128*129/2

// ---------------- device scratch (allocation-free: __device__ globals) -------
__device__ float g_Gpart[NPART][BATCH][C][C];   // 16 MB partial Gram
__device__ float g_spart[NPART][BATCH][C];      // partial row sums
__device__ float g_tr[BATCH];
__device__ float g_Y[2][BATCH][C][C];           // ping-pong Y
__device__ float g_Z[2][BATCH][C][C];           // ping-pong Z
__device__ float g_T[BATCH][C][C];

// =================== Kernel 1: partial Gram + row sums =======================
// grid (NPART, BATCH), 256 threads. Each block: full 128x128 Gram over its
// K-slice of 784 (25 chunks of 32, last masked). Per-thread 8x8 tile.
__global__ __launch_bounds__(256, 2)
void cov_partial(const float* __restrict__ x) {
    const int kp = blockIdx.x;
    const int b  = blockIdx.y;
    const float* xb = x + (size_t)b * C * HW;

    __shared__ float Xt[32][132];   // transposed chunk: Xt[kk][row]

    const int t  = threadIdx.x;
    const int tx = t & 15;
    const int ty = t >> 4;

    float acc[8][8];
#pragma unroll
    for (int i = 0; i < 8; i++)
#pragma unroll
        for (int j = 0; j < 8; j++) acc[i][j] = 0.0f;

    float rsum = 0.0f;

    const int kbeg = kp * KPART;
    const int kend = kbeg + KPART;

    for (int k0 = kbeg; k0 < kend; k0 += 32) {
        // load 128x32 chunk, transposed into smem (coalesced gmem reads)
        const int kk = t & 31;
        const int r0 = t >> 5;
        const int k  = k0 + kk;
        const bool ok = (k < kend);
#pragma unroll
        for (int p = 0; p < 16; p++) {
            const int row = r0 + p * 8;
            Xt[kk][row] = ok ? xb[(size_t)row * HW + k] : 0.0f;
        }
        __syncthreads();

        // row sums (threads 0..127 each own one row)
        if (t < C) {
#pragma unroll
            for (int q = 0; q < 32; q++) rsum += Xt[q][t];
        }

        // SYRK inner product: both operands from the same transposed tile
#pragma unroll 8
        for (int q = 0; q < 32; q++) {
            float av[8], bv[8];
            *(float4*)&av[0] = *(const float4*)&Xt[q][ty * 8];
            *(float4*)&av[4] = *(const float4*)&Xt[q][ty * 8 + 4];
            *(float4*)&bv[0] = *(const float4*)&Xt[q][tx * 8];
            *(float4*)&bv[4] = *(const float4*)&Xt[q][tx * 8 + 4];
#pragma unroll
            for (int ii = 0; ii < 8; ii++)
#pragma unroll
                for (int jj = 0; jj < 8; jj++)
                    acc[ii][jj] = fmaf(av[ii], bv[jj], acc[ii][jj]);
        }
        __syncthreads();
    }

    float* Gp = &g_Gpart[kp][b][0][0];
#pragma unroll
    for (int ii = 0; ii < 8; ii++) {
        const int i = ty * 8 + ii;
        *(float4*)&Gp[i * C + tx * 8]     = *(float4*)&acc[ii][0];
        *(float4*)&Gp[i * C + tx * 8 + 4] = *(float4*)&acc[ii][4];
    }
    if (t < C) g_spart[kp][b][t] = rsum;
}

// =================== Kernel 2: finalize sigma, trace, init Y/Z ===============
// grid (BATCH), 256 threads.
__global__ void cov_finalize() {
    const int b = blockIdx.x;
    const int t = threadIdx.x;
    __shared__ float sm_s[C];
    __shared__ float red[256];
    __shared__ float sm_tr;
    const float invn = 1.0f / (float)HW;

    if (t < C) {
        float s = 0.0f;
#pragma unroll
        for (int kp = 0; kp < NPART; kp++) s += g_spart[kp][b][t];
        sm_s[t] = s * invn;   // mean per channel
    }
    __syncthreads();

    // trace of sigma
    float tdiag = 0.0f;
    if (t < C) {
        float g = 0.0f;
#pragma unroll
        for (int kp = 0; kp < NPART; kp++) g += g_Gpart[kp][b][t][t];
        tdiag = g * invn - sm_s[t] * sm_s[t];
    }
    red[t] = tdiag;
    __syncthreads();
    for (int s = 128; s > 0; s >>= 1) {
        if (t < s) red[t] += red[t + s];
        __syncthreads();
    }
    if (t == 0) { sm_tr = red[0]; g_tr[b] = red[0]; }
    __syncthreads();
    const float invtr = 1.0f / sm_tr;

    for (int e = t; e < C * C; e += 256) {
        const int i = e >> 7;
        const int j = e & 127;
        float g = 0.0f;
#pragma unroll
        for (int kp = 0; kp < NPART; kp++) g += g_Gpart[kp][b][i][j];
        const float sig = g * invn - sm_s[i] * sm_s[j];
        g_Y[0][b][i][j] = sig * invtr;
        g_Z[0][b][i][j] = (i == j) ? 1.0f : 0.0f;
    }
}

// =================== Shared 128x128x128 GEMM tile ============================
__device__ __forceinline__ void mm128(const float* __restrict__ A,
                                      const float* __restrict__ B,
                                      float acc[8][8], int t) {
    __shared__ float At[32][132];   // At[kk][i]  (A transposed)
    __shared__ float Bs[32][132];   // Bs[kk][j]  (B natural)

    const int tx = t & 15;
    const int ty = t >> 4;

#pragma unroll
    for (int i = 0; i < 8; i++)
#pragma unroll
        for (int j = 0; j < 8; j++) acc[i][j] = 0.0f;

    for (int k0 = 0; k0 < C; k0 += 32) {
        const int kk = t & 31;
        const int r0 = t >> 5;
#pragma unroll
        for (int p = 0; p < 16; p++) {
            const int row = r0 + p * 8;
            At[kk][row] = A[row * C + k0 + kk];
        }
        const int j4  = (t & 31) * 4;
        const int kb0 = t >> 5;
#pragma unroll
        for (int p = 0; p < 4; p++) {
            const int kkb = kb0 + p * 8;
            *(float4*)&Bs[kkb][j4] = *(const float4*)&B[(k0 + kkb) * C + j4];
        }
        __syncthreads();

#pragma unroll 8
        for (int q = 0; q < 32; q++) {
            float av[8], bv[8];
            *(float4*)&av[0] = *(float4*)&At[q][ty * 8];
            *(float4*)&av[4] = *(float4*)&At[q][ty * 8 + 4];
            *(float4*)&bv[0] = *(float4*)&Bs[q][tx * 8];
            *(float4*)&bv[4] = *(float4*)&Bs[q][tx * 8 + 4];
#pragma unroll
            for (int ii = 0; ii < 8; ii++)
#pragma unroll
                for (int jj = 0; jj < 8; jj++)
                    acc[ii][jj] = fmaf(av[ii], bv[jj], acc[ii][jj]);
        }
        __syncthreads();
    }
}

// =================== Newton-Schulz kernels ===================================
// T = 0.5*(3I - Z@Y).  grid (BATCH), 256 threads.
__global__ __launch_bounds__(256, 2)
void ns_T(int ysel) {
    const int b = blockIdx.x;
    const int t = threadIdx.x;
    float acc[8][8];
    mm128(&g_Z[ysel][b][0][0], &g_Y[ysel][b][0][0], acc, t);
    const int tx = t & 15, ty = t >> 4;
#pragma unroll
    for (int ii = 0; ii < 8; ii++) {
        const int i = ty * 8 + ii;
        float row[8];
#pragma unroll
        for (int jj = 0; jj < 8; jj++) {
            const int j = tx * 8 + jj;
            row[jj] = ((i == j) ? 1.5f : 0.0f) - 0.5f * acc[ii][jj];
        }
        *(float4*)&g_T[b][i][tx * 8]     = *(float4*)&row[0];
        *(float4*)&g_T[b][i][tx * 8 + 4] = *(float4*)&row[4];
    }
}

// which==0: Ynext = Y@T ; which==1: Znext = T@Z.  grid (2, BATCH).
__global__ __launch_bounds__(256, 2)
void ns_YZ(int ysel) {
    const int which = blockIdx.x;
    const int b     = blockIdx.y;
    const int t     = threadIdx.x;
    const float* A;
    const float* Bm;
    float* Cm;
    if (which == 0) {
        A  = &g_Y[ysel][b][0][0];
        Bm = &g_T[b][0][0];
        Cm = &g_Y[1 - ysel][b][0][0];
    } else {
        A  = &g_T[b][0][0];
        Bm = &g_Z[ysel][b][0][0];
        Cm = &g_Z[1 - ysel][b][0][0];
    }
    float acc[8][8];
    mm128(A, Bm, acc, t);
    const int tx = t & 15, ty = t >> 4;
#pragma unroll
    for (int ii = 0; ii < 8; ii++) {
        const int i = ty * 8 + ii;
        *(float4*)&Cm[i * C + tx * 8]     = *(float4*)&acc[ii][0];
        *(float4*)&Cm[i * C + tx * 8 + 4] = *(float4*)&acc[ii][4];
    }
}

// =================== Final: scale by sqrt(tr), extract triu ==================
__global__ void final_k(int ysel, float* __restrict__ out) {
    const int b = blockIdx.x;
    const float s = sqrtf(g_tr[b]);
    const float* Y = &g_Y[ysel][b][0][0];
    float* o = out + (size_t)b * TRIU;
    for (int pos = threadIdx.x; pos < TRIU; pos += blockDim.x) {
        // rowoff(i) = i*(257-i)/2 ; invert approximately then fix up
        int i = (int)((257.0f - sqrtf(257.0f * 257.0f - 8.0f * (float)pos)) * 0.5f);
        if (i < 0) i = 0;
        if (i > 127) i = 127;
        while (i > 0 && i * (257 - i) / 2 > pos) i--;
        while (i < 127 && (i + 1) * (257 - (i + 1)) / 2 <= pos) i++;
        const int j = i + (pos - i * (257 - i) / 2);
        o[pos] = Y[i * C + j] * s;
    }
}

// =================== launch ==================================================
extern "C" void kernel_launch(void* const* d_in, const int* in_sizes, int n_in,
                              void* d_out, int out_size) {
    const float* x = (const float*)d_in[0];
    float* out = (float*)d_out;

    dim3 gcov(NPART, BATCH);
    cov_partial<<<gcov, 256>>>(x);
    cov_finalize<<<BATCH, 256>>>();

    int cur = 0;
    for (int it = 0; it < NUM_ITER; it++) {
        ns_T<<<BATCH, 256>>>(cur);
        dim3 gyz(2, BATCH);
        ns_YZ<<<gyz, 256>>>(cur);
        cur ^= 1;
    }
    final_k<<<BATCH, 256>>>(cur, out);
}

// round 2
// speedup vs baseline: 1.0242x; 1.0242x over previous
#include <cuda_runtime.h>
#include <math.h>

// Problem constants
#define BATCH 64
#define C 128
#define HW 3136           // 56*56
#define NPART 4
#define KPART (HW / NPART)  // 784
#define NUM_ITER 5
#define TRIU 8256         // 128*129/2

// ---------------- device scratch (allocation-free: __device__ globals) -------
__device__ float g_Gpart[NPART][BATCH][C][C];   // 16 MB partial Gram
__device__ float g_spart[NPART][BATCH][C];      // partial row sums
__device__ float g_tr[BATCH];
__device__ float g_Y[2][BATCH][C][C];           // ping-pong Y
__device__ float g_Z[2][BATCH][C][C];           // ping-pong Z
__device__ float g_T[BATCH][C][C];

// =================== Kernel 1: partial Gram + row sums =======================
// grid (NPART, BATCH), 256 threads. Each block: full 128x128 Gram over its
// K-slice of 784 (25 chunks of 32, last masked). Per-thread 8x8 tile.
__global__ __launch_bounds__(256, 2)
void cov_partial(const float* __restrict__ x) {
    const int kp = blockIdx.x;
    const int b  = blockIdx.y;
    const float* xb = x + (size_t)b * C * HW;

    __shared__ float Xt[32][132];   // transposed chunk: Xt[kk][row]

    const int t  = threadIdx.x;
    const int tx = t & 15;
    const int ty = t >> 4;

    float acc[8][8];
#pragma unroll
    for (int i = 0; i < 8; i++)
#pragma unroll
        for (int j = 0; j < 8; j++) acc[i][j] = 0.0f;

    float rsum = 0.0f;

    const int kbeg = kp * KPART;
    const int kend = kbeg + KPART;

    for (int k0 = kbeg; k0 < kend; k0 += 32) {
        // load 128x32 chunk, transposed into smem (coalesced gmem reads)
        const int kk = t & 31;
        const int r0 = t >> 5;
        const int k  = k0 + kk;
        const bool ok = (k < kend);
#pragma unroll
        for (int p = 0; p < 16; p++) {
            const int row = r0 + p * 8;
            Xt[kk][row] = ok ? xb[(size_t)row * HW + k] : 0.0f;
        }
        __syncthreads();

        // row sums (threads 0..127 each own one row)
        if (t < C) {
#pragma unroll
            for (int q = 0; q < 32; q++) rsum += Xt[q][t];
        }

        // SYRK inner product: both operands from the same transposed tile
#pragma unroll 8
        for (int q = 0; q < 32; q++) {
            float av[8], bv[8];
            *(float4*)&av[0] = *(const float4*)&Xt[q][ty * 8];
            *(float4*)&av[4] = *(const float4*)&Xt[q][ty * 8 + 4];
            *(float4*)&bv[0] = *(const float4*)&Xt[q][tx * 8];
            *(float4*)&bv[4] = *(const float4*)&Xt[q][tx * 8 + 4];
#pragma unroll
            for (int ii = 0; ii < 8; ii++)
#pragma unroll
                for (int jj = 0; jj < 8; jj++)
                    acc[ii][jj] = fmaf(av[ii], bv[jj], acc[ii][jj]);
        }
        __syncthreads();
    }

    float* Gp = &g_Gpart[kp][b][0][0];
#pragma unroll
    for (int ii = 0; ii < 8; ii++) {
        const int i = ty * 8 + ii;
        *(float4*)&Gp[i * C + tx * 8]     = *(float4*)&acc[ii][0];
        *(float4*)&Gp[i * C + tx * 8 + 4] = *(float4*)&acc[ii][4];
    }
    if (t < C) g_spart[kp][b][t] = rsum;
}

// =================== Kernel 2: finalize sigma, trace, init Y/Z ===============
// grid (BATCH), 256 threads.
__global__ void cov_finalize() {
    const int b = blockIdx.x;
    const int t = threadIdx.x;
    __shared__ float sm_s[C];
    __shared__ float red[256];
    __shared__ float sm_tr;
    const float invn = 1.0f / (float)HW;

    if (t < C) {
        float s = 0.0f;
#pragma unroll
        for (int kp = 0; kp < NPART; kp++) s += g_spart[kp][b][t];
        sm_s[t] = s * invn;   // mean per channel
    }
    __syncthreads();

    // trace of sigma
    float tdiag = 0.0f;
    if (t < C) {
        float g = 0.0f;
#pragma unroll
        for (int kp = 0; kp < NPART; kp++) g += g_Gpart[kp][b][t][t];
        tdiag = g * invn - sm_s[t] * sm_s[t];
    }
    red[t] = tdiag;
    __syncthreads();
    for (int s = 128; s > 0; s >>= 1) {
        if (t < s) red[t] += red[t + s];
        __syncthreads();
    }
    if (t == 0) { sm_tr = red[0]; g_tr[b] = red[0]; }
    __syncthreads();
    const float invtr = 1.0f / sm_tr;

    for (int e = t; e < C * C; e += 256) {
        const int i = e >> 7;
        const int j = e & 127;
        float g = 0.0f;
#pragma unroll
        for (int kp = 0; kp < NPART; kp++) g += g_Gpart[kp][b][i][j];
        const float sig = g * invn - sm_s[i] * sm_s[j];
        g_Y[0][b][i][j] = sig * invtr;
        g_Z[0][b][i][j] = (i == j) ? 1.0f : 0.0f;
    }
}

// =================== Shared 128x128x128 GEMM tile ============================
__device__ __forceinline__ void mm128(const float* __restrict__ A,
                                      const float* __restrict__ B,
                                      float acc[8][8], int t) {
    __shared__ float At[32][132];   // At[kk][i]  (A transposed)
    __shared__ float Bs[32][132];   // Bs[kk][j]  (B natural)

    const int tx = t & 15;
    const int ty = t >> 4;

#pragma unroll
    for (int i = 0; i < 8; i++)
#pragma unroll
        for (int j = 0; j < 8; j++) acc[i][j] = 0.0f;

    for (int k0 = 0; k0 < C; k0 += 32) {
        const int kk = t & 31;
        const int r0 = t >> 5;
#pragma unroll
        for (int p = 0; p < 16; p++) {
            const int row = r0 + p * 8;
            At[kk][row] = A[row * C + k0 + kk];
        }
        const int j4  = (t & 31) * 4;
        const int kb0 = t >> 5;
#pragma unroll
        for (int p = 0; p < 4; p++) {
            const int kkb = kb0 + p * 8;
            *(float4*)&Bs[kkb][j4] = *(const float4*)&B[(k0 + kkb) * C + j4];
        }
        __syncthreads();

#pragma unroll 8
        for (int q = 0; q < 32; q++) {
            float av[8], bv[8];
            *(float4*)&av[0] = *(float4*)&At[q][ty * 8];
            *(float4*)&av[4] = *(float4*)&At[q][ty * 8 + 4];
            *(float4*)&bv[0] = *(float4*)&Bs[q][tx * 8];
            *(float4*)&bv[4] = *(float4*)&Bs[q][tx * 8 + 4];
#pragma unroll
            for (int ii = 0; ii < 8; ii++)
#pragma unroll
                for (int jj = 0; jj < 8; jj++)
                    acc[ii][jj] = fmaf(av[ii], bv[jj], acc[ii][jj]);
        }
        __syncthreads();
    }
}

// =================== Newton-Schulz kernels ===================================
// T = 0.5*(3I - Z@Y).  grid (BATCH), 256 threads.
__global__ __launch_bounds__(256, 2)
void ns_T(int ysel) {
    const int b = blockIdx.x;
    const int t = threadIdx.x;
    float acc[8][8];
    mm128(&g_Z[ysel][b][0][0], &g_Y[ysel][b][0][0], acc, t);
    const int tx = t & 15, ty = t >> 4;
#pragma unroll
    for (int ii = 0; ii < 8; ii++) {
        const int i = ty * 8 + ii;
        float row[8];
#pragma unroll
        for (int jj = 0; jj < 8; jj++) {
            const int j = tx * 8 + jj;
            row[jj] = ((i == j) ? 1.5f : 0.0f) - 0.5f * acc[ii][jj];
        }
        *(float4*)&g_T[b][i][tx * 8]     = *(float4*)&row[0];
        *(float4*)&g_T[b][i][tx * 8 + 4] = *(float4*)&row[4];
    }
}

// which==0: Ynext = Y@T ; which==1: Znext = T@Z.  grid (2, BATCH).
__global__ __launch_bounds__(256, 2)
void ns_YZ(int ysel) {
    const int which = blockIdx.x;
    const int b     = blockIdx.y;
    const int t     = threadIdx.x;
    const float* A;
    const float* Bm;
    float* Cm;
    if (which == 0) {
        A  = &g_Y[ysel][b][0][0];
        Bm = &g_T[b][0][0];
        Cm = &g_Y[1 - ysel][b][0][0];
    } else {
        A  = &g_T[b][0][0];
        Bm = &g_Z[ysel][b][0][0];
        Cm = &g_Z[1 - ysel][b][0][0];
    }
    float acc[8][8];
    mm128(A, Bm, acc, t);
    const int tx = t & 15, ty = t >> 4;
#pragma unroll
    for (int ii = 0; ii < 8; ii++) {
        const int i = ty * 8 + ii;
        *(float4*)&Cm[i * C + tx * 8]     = *(float4*)&acc[ii][0];
        *(float4*)&Cm[i * C + tx * 8 + 4] = *(float4*)&acc[ii][4];
    }
}

// =================== Final: scale by sqrt(tr), extract triu ==================
__global__ void final_k(int ysel, float* __restrict__ out) {
    const int b = blockIdx.x;
    const float s = sqrtf(g_tr[b]);
    const float* Y = &g_Y[ysel][b][0][0];
    float* o = out + (size_t)b * TRIU;
    for (int pos = threadIdx.x; pos < TRIU; pos += blockDim.x) {
        // rowoff(i) = i*(257-i)/2 ; invert approximately then fix up
        int i = (int)((257.0f - sqrtf(257.0f * 257.0f - 8.0f * (float)pos)) * 0.5f);
        if (i < 0) i = 0;
        if (i > 127) i = 127;
        while (i > 0 && i * (257 - i) / 2 > pos) i--;
        while (i < 127 && (i + 1) * (257 - (i + 1)) / 2 <= pos) i++;
        const int j = i + (pos - i * (257 - i) / 2);
        o[pos] = Y[i * C + j] * s;
    }
}

// =================== launch ==================================================
extern "C" void kernel_launch(void* const* d_in, const int* in_sizes, int n_in,
                              void* d_out, int out_size) {
    const float* x = (const float*)d_in[0];
    float* out = (float*)d_out;

    dim3 gcov(NPART, BATCH);
    cov_partial<<<gcov, 256>>>(x);
    cov_finalize<<<BATCH, 256>>>();

    int cur = 0;
    for (int it = 0; it < NUM_ITER; it++) {
        ns_T<<<BATCH, 256>>>(cur);
        dim3 gyz(2, BATCH);
        ns_YZ<<<gyz, 256>>>(cur);
        cur ^= 1;
    }
    final_k<<<BATCH, 256>>>(cur, out);
}